// round 11
// baseline (speedup 1.0000x reference)
#include <cuda_runtime.h>
#include <cstdint>
#include <math.h>

#define N 4096
#define IN_F 256
#define HH 4
#define OF 128
#define HOF 512
#define SLOPE 0.2f

// Scratch (device globals: no allocations allowed)
__device__ float g_h[N * HOF];           // 8 MB   [n][h*128+f]  (fp32 accum result)
__device__ float g_hT[HH * OF * N];      // 8 MB   [h][f][j-permuted] (tf32-rounded)
__device__ float g_ci[N * HH];
__device__ float g_cj[N * HH];

__device__ __forceinline__ uint32_t smem_u32(const void* p) {
    uint32_t a;
    asm("{ .reg .u64 t; cvta.to.shared.u64 t, %1; cvt.u32.u64 %0, t; }" : "=r"(a) : "l"(p));
    return a;
}
__device__ __forceinline__ float to_tf32(float x) {
    float r;
    asm("cvt.rna.tf32.f32 %0, %1;" : "=f"(r) : "f"(x));
    return r;
}
#define CP_ASYNC16(dst_u32, src_ptr) \
    asm volatile("cp.async.cg.shared.global [%0], [%1], 16;" :: "r"(dst_u32), \
                 "l"(__cvta_generic_to_global(src_ptr)))
#define CP_COMMIT() asm volatile("cp.async.commit_group;" ::: "memory")
#define CP_WAIT2()  asm volatile("cp.async.wait_group 2;" ::: "memory")

// m16n8k8 tf32 MMA, D += A*B (row.col)
__device__ __forceinline__ void mma_tf32(float* c, const uint32_t* a, const uint32_t* b) {
    asm volatile(
        "mma.sync.aligned.m16n8k8.row.col.f32.tf32.tf32.f32 "
        "{%0,%1,%2,%3}, {%4,%5,%6,%7}, {%8,%9}, {%0,%1,%2,%3};"
        : "+f"(c[0]), "+f"(c[1]), "+f"(c[2]), "+f"(c[3])
        : "r"(a[0]), "r"(a[1]), "r"(a[2]), "r"(a[3]), "r"(b[0]), "r"(b[1]));
}

// k-pair interleave inside each 8-group: w -> 2*(w&3) + (w>>2); inverse below
__device__ __forceinline__ int kperm(int w) { return ((w & 3) << 1) | ((w >> 2) & 1); }
__device__ __forceinline__ int kperm_inv(int v) { return ((v & 7) >> 1) | ((v & 1) << 2); }
__device__ __forceinline__ int kcol_of(int k) { return (k & ~7) | kperm(k & 7); }

// ---------------------------------------------------------------------------
// Kernel A (tf32 mma): g_h = x @ W ; g_hT = tf32-rounded transpose (j-permuted)
// BM=64, BN=64, BK=32; 8 warps 2(M)x4(N); warp tile 32x16.
// Epilogue stages the 64x64 tile in SMEM and writes BOTH outputs coalesced.
// ---------------------------------------------------------------------------
#define GLDW 40
#define TSW 65
__global__ __launch_bounds__(256) void k_gemm_h(const float* __restrict__ X,
                                                const float* __restrict__ W) {
    __shared__ float SMA[2 * 64 * GLDW];   // 5120 floats; reused as TS[64][65]=4160
    float* XS = SMA;
    float* WS = SMA + 64 * GLDW;
    const int tid = threadIdx.x;
    const int wid = tid >> 5;
    const int lane = tid & 31;
    const int g = lane >> 2;
    const int t = lane & 3;
    const int row0 = blockIdx.y * 64;
    const int col0 = blockIdx.x * 64;
    const int mrow0 = (wid & 1) * 32;
    const int ncol0 = (wid >> 1) * 16;

    float acc[2][2][4];
#pragma unroll
    for (int a = 0; a < 2; a++)
#pragma unroll
        for (int b = 0; b < 2; b++)
#pragma unroll
            for (int c = 0; c < 4; c++) acc[a][b][c] = 0.0f;

    for (int k0 = 0; k0 < IN_F; k0 += 32) {
#pragma unroll
        for (int it = 0; it < 2; it++) {
            int idx = tid + 256 * it;
            int m = idx >> 3, q = idx & 7;
            float4 v = *(const float4*)&X[(size_t)(row0 + m) * IN_F + k0 + q * 4];
            float e[4] = {v.x, v.y, v.z, v.w};
#pragma unroll
            for (int j = 0; j < 4; j++)
                XS[m * GLDW + kcol_of(q * 4 + j)] = to_tf32(e[j]);
        }
#pragma unroll
        for (int it = 0; it < 2; it++) {
            int idx = tid + 256 * it;
            int k = idx >> 4, n4 = idx & 15;
            float4 v = *(const float4*)&W[(size_t)(k0 + k) * HOF + col0 + n4 * 4];
            float e[4] = {v.x, v.y, v.z, v.w};
            int kc = kcol_of(k);
#pragma unroll
            for (int j = 0; j < 4; j++)
                WS[(n4 * 4 + j) * GLDW + kc] = to_tf32(e[j]);
        }
        __syncthreads();
#pragma unroll
        for (int ks = 0; ks < 4; ks++) {
            const int kc = ks * 8 + 2 * t;
            uint32_t bfr[2][2];
#pragma unroll
            for (int nt = 0; nt < 2; nt++) {
                int n = ncol0 + nt * 8 + g;
                float2 bv = *(const float2*)&WS[n * GLDW + kc];
                bfr[nt][0] = __float_as_uint(bv.x);
                bfr[nt][1] = __float_as_uint(bv.y);
            }
#pragma unroll
            for (int mt = 0; mt < 2; mt++) {
                int r0 = mrow0 + mt * 16;
                float2 a0 = *(const float2*)&XS[(r0 + g) * GLDW + kc];
                float2 a1 = *(const float2*)&XS[(r0 + g + 8) * GLDW + kc];
                uint32_t afr[4];
                afr[0] = __float_as_uint(a0.x);
                afr[1] = __float_as_uint(a1.x);
                afr[2] = __float_as_uint(a0.y);
                afr[3] = __float_as_uint(a1.y);
#pragma unroll
                for (int nt = 0; nt < 2; nt++) mma_tf32(acc[mt][nt], afr, bfr[nt]);
            }
        }
        __syncthreads();
    }

    // --- epilogue: stage tile transposed in SMEM, write coalesced ---
    float* TS = SMA;   // TS[c_local][j_local], stride TSW (all mma done: loop
                       // ended with __syncthreads)
#pragma unroll
    for (int mt = 0; mt < 2; mt++) {
        const int ja = mrow0 + mt * 16 + g;
        const int jb = ja + 8;
#pragma unroll
        for (int nt = 0; nt < 2; nt++) {
            const int cl = ncol0 + nt * 8 + 2 * t;
            TS[cl * TSW + ja] = acc[mt][nt][0];
            TS[(cl + 1) * TSW + ja] = acc[mt][nt][1];
            TS[cl * TSW + jb] = acc[mt][nt][2];
            TS[(cl + 1) * TSW + jb] = acc[mt][nt][3];
        }
    }
    __syncthreads();

    // g_h: warp handles 8 j-rows, 128B coalesced stores
#pragma unroll
    for (int r = 0; r < 8; r++) {
        const int j = wid * 8 + r;
#pragma unroll
        for (int it = 0; it < 2; it++) {
            const int cl = it * 32 + lane;
            g_h[(size_t)(row0 + j) * HOF + col0 + cl] = TS[cl * TSW + j];
        }
    }
    // g_hT: warp handles 8 f-rows, perm folded into the TS read index
    {
        const int hd = col0 >> 7;
        const int f0 = col0 & 127;
#pragma unroll
        for (int r = 0; r < 8; r++) {
            const int cl = wid * 8 + r;
            float* dst = g_hT + ((size_t)hd * OF + f0 + cl) * N + row0;
#pragma unroll
            for (int it = 0; it < 2; it++) {
                const int jd = it * 32 + lane;
                const int jl = (jd & ~7) | kperm_inv(jd);
                dst[jd] = to_tf32(TS[cl * TSW + jl]);
            }
        }
    }
}

// ---------------------------------------------------------------------------
// Kernel B: ci / cj coefficients. One warp per (n,h).
// ---------------------------------------------------------------------------
__global__ __launch_bounds__(128) void k_coeff(const float* __restrict__ a_i,
                                               const float* __restrict__ a_j) {
    const int n = blockIdx.x;
    const int h = threadIdx.x >> 5;
    const int lane = threadIdx.x & 31;

    float4 hv = *(const float4*)&g_h[n * HOF + h * OF + lane * 4];
    float4 ai = *(const float4*)&a_i[h * OF + lane * 4];
    float4 aj = *(const float4*)&a_j[h * OF + lane * 4];
    float si = hv.x * ai.x + hv.y * ai.y + hv.z * ai.z + hv.w * ai.w;
    float sj = hv.x * aj.x + hv.y * aj.y + hv.z * aj.z + hv.w * aj.w;
#pragma unroll
    for (int o = 16; o > 0; o >>= 1) {
        si += __shfl_down_sync(0xffffffffu, si, o);
        sj += __shfl_down_sync(0xffffffffu, sj, o);
    }
    if (lane == 0) {
        g_ci[n * HH + h] = si;
        g_cj[n * HH + h] = sj;
    }
}

// ---------------------------------------------------------------------------
// Kernel D (mma.sync tf32, fused z, software-pipelined):
// iteration i does P(i) AND mma(i-1) in one inter-barrier window.
// P double-buffered; H 4-stage cp.async ring committed 2 ahead (wait_group 2);
// adj via register double-buffered LDG. One __syncthreads per chunk.
// ---------------------------------------------------------------------------
#define D_BM 64
#define D_BK 32
#define NCHUNK (N / D_BK)
#define LDW 40

#define OFF_CI   0
#define OFF_BIAS 64
#define OFF_Z    192
#define OFF_H    256                    // 4 stages x 128x40 = 4x5120
#define OFF_P    (OFF_H + 4*5120)       // 2 stages x 64x40  = 2x2560
#define SM_FLOATS (OFF_P + 2*2560)
#define SM_BYTES (SM_FLOATS * 4)

__global__ __launch_bounds__(256, 2) void k_out_tc(const float* __restrict__ adj,
                                                   const float* __restrict__ bias,
                                                   float* __restrict__ out) {
    extern __shared__ float smf[];
    const uint32_t sb = smem_u32(smf);
    const int tid = threadIdx.x;
    const int wid = tid >> 5;
    const int lane = tid & 31;
    const int g = lane >> 2;
    const int t = lane & 3;
    const int i0 = blockIdx.x * D_BM;
    const int head = blockIdx.y;
    const int mrow0 = (wid & 1) * 32;
    const int n0w = (wid >> 1) * 32;

    if (tid < 64) smf[OFF_CI + tid] = g_ci[(i0 + tid) * HH + head];
    if (tid >= 64 && tid < 192) smf[OFF_BIAS + tid - 64] = bias[head * OF + tid - 64];

    // prologue: H(0), H(1) as separate cp.async groups
#pragma unroll
    for (int c = 0; c < 2; c++) {
        const uint32_t h_dst = sb + (uint32_t)(OFF_H + c * 5120) * 4;
#pragma unroll
        for (int it = 0; it < 4; it++) {
            int idx = tid + 256 * it;
            int f = idx >> 3, q = idx & 7;
            CP_ASYNC16(h_dst + (uint32_t)(f * LDW + q * 4) * 4,
                       g_hT + ((size_t)head * OF + f) * N + c * D_BK + q * 4);
        }
        CP_COMMIT();
    }

    // adj + cj for chunk 0
    float aval[8];
#pragma unroll
    for (int it = 0; it < 8; it++)
        aval[it] = adj[(size_t)(i0 + wid + 8 * it) * N + lane];
    float cjv = g_cj[(size_t)lane * HH + head];

    __syncthreads();

    float acc[2][4][4];
#pragma unroll
    for (int a = 0; a < 2; a++)
#pragma unroll
        for (int b = 0; b < 4; b++)
#pragma unroll
            for (int c = 0; c < 4; c++) acc[a][b][c] = 0.0f;
    float zacc[8];
#pragma unroll
    for (int it = 0; it < 8; it++) zacc[it] = 0.0f;

    const float* ci_s = smf + OFF_CI;
    const int pcol = ((lane >> 3) << 3) | kperm(lane & 7);

    for (int i = 0; i <= NCHUNK; i++) {
        // prefetch adj/cj for chunk i+1 (registers; independent of waits)
        float anx[8];
        float cjn = 0.0f;
        if (i + 1 < NCHUNK) {
            const int j1 = (i + 1) * D_BK;
#pragma unroll
            for (int it = 0; it < 8; it++)
                anx[it] = adj[(size_t)(i0 + wid + 8 * it) * N + j1 + lane];
            cjn = g_cj[(size_t)(j1 + lane) * HH + head];
        }

        if (i >= 1) CP_WAIT2();   // H(i-1) complete (pending <= {H(i), H(i+1)})
        __syncthreads();          // P(i-1) visible; ring stage (i+2)&3 free

        // issue H(i+2) into stage (i+2)&3 (readers mma(i-2) were pre-bar)
        if (i + 2 < NCHUNK) {
            const uint32_t h_dst = sb + (uint32_t)(OFF_H + ((i + 2) & 3) * 5120) * 4;
            const int j2 = (i + 2) * D_BK;
#pragma unroll
            for (int it = 0; it < 4; it++) {
                int idx = tid + 256 * it;
                int f = idx >> 3, q = idx & 7;
                CP_ASYNC16(h_dst + (uint32_t)(f * LDW + q * 4) * 4,
                           g_hT + ((size_t)head * OF + f) * N + j2 + q * 4);
            }
            CP_COMMIT();
        }

        // P(i): exp + z accumulation into stage i&1 (overlaps mma below)
        if (i < NCHUNK) {
            float* PS = smf + OFF_P + (i & 1) * 2560;
#pragma unroll
            for (int it = 0; it < 8; it++) {
                const int r = wid + 8 * it;
                float sc = ci_s[r] + cjv;
                sc = fmaxf(sc, SLOPE * sc) * aval[it];
                float e = __expf(sc);
                zacc[it] += e;
                PS[r * LDW + pcol] = to_tf32(e * aval[it]);
            }
        }

        // mma(i-1): PS[(i-1)&1] x HS[(i-1)&3]
        if (i >= 1) {
            const float* PSr = smf + OFF_P + ((i - 1) & 1) * 2560;
            const float* HS = smf + OFF_H + ((i - 1) & 3) * 5120;
#pragma unroll
            for (int ks = 0; ks < 4; ks++) {
                const int kc = ks * 8 + 2 * t;
                uint32_t bfr[4][2];
#pragma unroll
                for (int nt = 0; nt < 4; nt++) {
                    int n = n0w + nt * 8 + g;
                    float2 bv = *(const float2*)&HS[n * LDW + kc];
                    bfr[nt][0] = __float_as_uint(bv.x);
                    bfr[nt][1] = __float_as_uint(bv.y);
                }
#pragma unroll
                for (int mt = 0; mt < 2; mt++) {
                    int r0 = mrow0 + mt * 16;
                    float2 a0 = *(const float2*)&PSr[(r0 + g) * LDW + kc];
                    float2 a1 = *(const float2*)&PSr[(r0 + g + 8) * LDW + kc];
                    uint32_t afr[4];
                    afr[0] = __float_as_uint(a0.x);
                    afr[1] = __float_as_uint(a1.x);
                    afr[2] = __float_as_uint(a0.y);
                    afr[3] = __float_as_uint(a1.y);
#pragma unroll
                    for (int nt = 0; nt < 4; nt++) mma_tf32(acc[mt][nt], afr, bfr[nt]);
                }
            }
        }

        if (i + 1 < NCHUNK) {
#pragma unroll
            for (int it = 0; it < 8; it++) aval[it] = anx[it];
            cjv = cjn;
        }
    }

    // z: reduce across lanes (each warp owns rows wid+8*it)
#pragma unroll
    for (int it = 0; it < 8; it++) {
        float v = zacc[it];
#pragma unroll
        for (int o = 16; o > 0; o >>= 1) v += __shfl_xor_sync(0xffffffffu, v, o);
        if (lane == 0) smf[OFF_Z + wid + 8 * it] = v;
    }
    __syncthreads();

    // epilogue: scale by 1/z, add bias
    const float* biasS = smf + OFF_BIAS;
    const float* zS = smf + OFF_Z;
#pragma unroll
    for (int mt = 0; mt < 2; mt++) {
        const int r = mrow0 + mt * 16 + g;
        const int ra = i0 + r;
        const float za = 1.0f / zS[r];
        const float zb = 1.0f / zS[r + 8];
#pragma unroll
        for (int nt = 0; nt < 4; nt++) {
            const int col = n0w + nt * 8 + 2 * t;
            float2 v0, v1;
            v0.x = acc[mt][nt][0] * za + biasS[col];
            v0.y = acc[mt][nt][1] * za + biasS[col + 1];
            v1.x = acc[mt][nt][2] * zb + biasS[col];
            v1.y = acc[mt][nt][3] * zb + biasS[col + 1];
            *(float2*)&out[(size_t)ra * HOF + head * OF + col] = v0;
            *(float2*)&out[(size_t)(ra + 8) * HOF + head * OF + col] = v1;
        }
    }
}

// ---------------------------------------------------------------------------
extern "C" void kernel_launch(void* const* d_in, const int* in_sizes, int n_in,
                              void* d_out, int out_size) {
    const float* x    = (const float*)d_in[0];   // (4096, 256)
    const float* adj  = (const float*)d_in[1];   // (4096, 4096)
    const float* W    = (const float*)d_in[2];   // (256, 512)
    const float* a_i  = (const float*)d_in[3];   // (4, 128, 1)
    const float* a_j  = (const float*)d_in[4];   // (4, 128, 1)
    const float* bias = (const float*)d_in[5];   // (512,)
    float* out = (float*)d_out;                  // (4096, 512)

    cudaFuncSetAttribute(k_out_tc, cudaFuncAttributeMaxDynamicSharedMemorySize, SM_BYTES);

    dim3 gA(HOF / 64, N / 64);
    k_gemm_h<<<gA, 256>>>(x, W);
    k_coeff<<<N, 128>>>(a_i, a_j);
    dim3 gD(N / D_BM, HH);
    k_out_tc<<<gD, 256, SM_BYTES>>>(adj, bias, out);
}